// round 5
// baseline (speedup 1.0000x reference)
#include <cuda_runtime.h>
#include <cuda_bf16.h>
#include <cuda_fp16.h>
#include <mma.h>
#include <cstdint>
#include <cstddef>
using namespace nvcuda;

#define B_  2048
#define T_  128
#define F_  64
#define H_  256
#define G3  768
#define OL  32
#define FCH 256

// ---- device scratch (static __device__; no allocs allowed) ----
__device__ float  g_h[2][B_ * H_];
__device__ float  g_gi[(size_t)B_ * T_ * G3];     // precomputed x@Wih^T (805MB)
__device__ float  g_gh[B_ * G3];                  // per-step h@Whh^T
__device__ __half g_hs[(size_t)B_ * T_ * H_];     // encoder outputs (fp16)
__device__ float  g_Asc[B_ * T_], g_Csc[B_ * T_]; // Wq.hs, bq.hs
__device__ float  g_ctx[B_ * H_], g_hd[B_ * H_], g_relu[B_ * FCH];
__device__ float  g_prev0[B_], g_prev[B_];
__device__ __nv_bfloat16 ih_hi[G3 * F_], ih_lo[G3 * F_];
__device__ __nv_bfloat16 eh_hi[G3 * H_], eh_lo[G3 * H_];
__device__ __nv_bfloat16 dh_hi[G3 * H_], dh_lo[G3 * H_];
__device__ __nv_bfloat16 f1_hi[FCH * H_], f1_lo[FCH * H_];

__device__ __forceinline__ void split1(float w, __nv_bfloat16* hi, __nv_bfloat16* lo, int i) {
    __nv_bfloat16 h = __float2bfloat16(w);
    hi[i] = h;
    lo[i] = __float2bfloat16(w - __bfloat162float(h));
}
__device__ __forceinline__ float sigf(float v) { return 1.f / (1.f + expf(-v)); }

// ---- prep: split weights into bf16 hi/lo ----
__global__ void prep_weights(const float* __restrict__ eWih, const float* __restrict__ eWhh,
                             const float* __restrict__ dWhh, const float* __restrict__ f1W)
{
    int i = blockIdx.x * blockDim.x + threadIdx.x;
    const int n0 = G3 * F_, n1 = G3 * H_, n2 = G3 * H_, n3 = FCH * H_;
    if (i < n0) split1(eWih[i], ih_hi, ih_lo, i);
    else if (i < n0 + n1) split1(eWhh[i - n0], eh_hi, eh_lo, i - n0);
    else if (i < n0 + n1 + n2) split1(dWhh[i - n0 - n1], dh_hi, dh_lo, i - n0 - n1);
    else if (i < n0 + n1 + n2 + n3) split1(f1W[i - n0 - n1 - n2], f1_hi, f1_lo, i - n0 - n1 - n2);
}

__global__ void prep_state(const float* __restrict__ x, const float* __restrict__ h0)
{
    int i = blockIdx.x * blockDim.x + threadIdx.x;
    if (i < B_ * H_) g_h[0][i] = h0[i];
    if (i < B_)      g_prev0[i] = x[((size_t)i * T_ + (T_ - 1)) * F_ + 0];
}

// ---- generic GEMM: C[M,N] = A[M,K] @ W[N,K]^T (+bias)(relu), 3-product bf16 split ----
// grid (M/128, N/64), block 256 (8 warps, 4x2 warp tiles of 32x32)
__global__ void __launch_bounds__(256) gemm_split(
    const float* __restrict__ A, int lda,
    const __nv_bfloat16* __restrict__ Wh, const __nv_bfloat16* __restrict__ Wl,
    float* __restrict__ C, int ldc, int K,
    const float* __restrict__ bias, int dorelu)
{
    __shared__ __align__(16) char smem[128 * 68 * 4];
    __nv_bfloat16* sAh = (__nv_bfloat16*)smem;   // 128x40
    __nv_bfloat16* sAl = sAh + 128 * 40;
    __nv_bfloat16* sBh = sAl + 128 * 40;          // 64x40
    __nv_bfloat16* sBl = sBh + 64 * 40;
    float* sC = (float*)smem;                     // 128x68 (reused after K loop)

    const int tid  = threadIdx.x;
    const int row0 = blockIdx.x * 128;
    const int ns   = blockIdx.y * 64;
    const int w    = tid >> 5;
    const int m0   = (w & 3) * 32, n0 = (w >> 2) * 32;

    wmma::fragment<wmma::accumulator, 16, 16, 16, float> acc[2][2];
    #pragma unroll
    for (int a = 0; a < 2; a++)
        #pragma unroll
        for (int b = 0; b < 2; b++) wmma::fill_fragment(acc[a][b], 0.f);

    for (int kc = 0; kc < K; kc += 32) {
        for (int idx = tid; idx < 128 * 32; idx += 256) {      // A chunk
            int m = idx >> 5, kk = idx & 31;
            float v = A[(size_t)(row0 + m) * lda + kc + kk];
            __nv_bfloat16 h = __float2bfloat16(v);
            sAh[m * 40 + kk] = h;
            sAl[m * 40 + kk] = __float2bfloat16(v - __bfloat162float(h));
        }
        for (int idx = tid; idx < 64 * 32; idx += 256) {       // W chunk (pre-split)
            int n = idx >> 5, kk = idx & 31;
            size_t gi = (size_t)(ns + n) * K + kc + kk;
            sBh[n * 40 + kk] = Wh[gi];
            sBl[n * 40 + kk] = Wl[gi];
        }
        __syncthreads();
        #pragma unroll
        for (int k16 = 0; k16 < 2; k16++) {
            wmma::fragment<wmma::matrix_a, 16, 16, 16, __nv_bfloat16, wmma::row_major> ah[2], al[2];
            #pragma unroll
            for (int mf = 0; mf < 2; mf++) {
                wmma::load_matrix_sync(ah[mf], sAh + (m0 + mf * 16) * 40 + k16 * 16, 40);
                wmma::load_matrix_sync(al[mf], sAl + (m0 + mf * 16) * 40 + k16 * 16, 40);
            }
            #pragma unroll
            for (int nf = 0; nf < 2; nf++) {
                wmma::fragment<wmma::matrix_b, 16, 16, 16, __nv_bfloat16, wmma::col_major> bh, bl;
                wmma::load_matrix_sync(bh, sBh + (n0 + nf * 16) * 40 + k16 * 16, 40);
                wmma::load_matrix_sync(bl, sBl + (n0 + nf * 16) * 40 + k16 * 16, 40);
                #pragma unroll
                for (int mf = 0; mf < 2; mf++) {
                    wmma::mma_sync(acc[mf][nf], ah[mf], bh, acc[mf][nf]);
                    wmma::mma_sync(acc[mf][nf], ah[mf], bl, acc[mf][nf]);
                    wmma::mma_sync(acc[mf][nf], al[mf], bh, acc[mf][nf]);
                }
            }
        }
        __syncthreads();
    }
    #pragma unroll
    for (int mf = 0; mf < 2; mf++)
        #pragma unroll
        for (int nf = 0; nf < 2; nf++)
            wmma::store_matrix_sync(sC + (m0 + mf * 16) * 68 + n0 + nf * 16,
                                    acc[mf][nf], 68, wmma::mem_row_major);
    __syncthreads();
    for (int idx = tid; idx < 128 * 64; idx += 256) {
        int m = idx >> 6, n = idx & 63;
        float v = sC[m * 68 + n];
        if (bias) v += bias[ns + n];
        if (dorelu) v = fmaxf(v, 0.f);
        C[(size_t)(row0 + m) * ldc + ns + n] = v;
    }
}

// ---- encoder elementwise GRU (reads g_gi, g_gh) ----
__global__ void enc_elem(const float* __restrict__ bih, const float* __restrict__ bhh,
                         int t, int pin)
{
    int i = blockIdx.x * blockDim.x + threadIdx.x;
    if (i >= B_ * H_) return;
    int b = i >> 8, k = i & 255;
    const float* gi = g_gi + ((size_t)b * T_ + t) * G3;
    const float* gh = g_gh + b * G3;
    float r = sigf(gi[k] + bih[k] + gh[k] + bhh[k]);
    float z = sigf(gi[H_ + k] + bih[H_ + k] + gh[H_ + k] + bhh[H_ + k]);
    float n = tanhf(gi[2 * H_ + k] + bih[2 * H_ + k] + r * (gh[2 * H_ + k] + bhh[2 * H_ + k]));
    float hn = (1.f - z) * n + z * g_h[pin][i];
    g_h[pin ^ 1][i] = hn;
    g_hs[((size_t)b * T_ + t) * H_ + k] = __float2half(hn);
}

// ---- attention precompute: Asc = Wq.hs, Csc = bq.hs ----
__global__ void attn_pre(const float* __restrict__ Wq, const float* __restrict__ bq)
{
    int warp = threadIdx.x >> 5, lane = threadIdx.x & 31;
    int row = blockIdx.x * 8 + warp;
    const __half* hp = g_hs + (size_t)row * H_;
    float sa = 0.f, sc = 0.f;
    #pragma unroll
    for (int h = lane; h < H_; h += 32) {
        float v = __half2float(hp[h]);
        sa += Wq[h] * v;
        sc += bq[h] * v;
    }
    #pragma unroll
    for (int o = 16; o > 0; o >>= 1) {
        sa += __shfl_down_sync(0xffffffffu, sa, o);
        sc += __shfl_down_sync(0xffffffffu, sc, o);
    }
    if (lane == 0) { g_Asc[row] = sa; g_Csc[row] = sc; }
}

// ---- decoder: prev (fc2 of prior relu) + softmax + ctx. one block per batch ----
__global__ void __launch_bounds__(256) dec_attn(const float* __restrict__ f2W,
                                                const float* __restrict__ f2b,
                                                float* __restrict__ dout,
                                                int s, int do_attn)
{
    __shared__ float ssc[128];
    __shared__ float sred[8];
    __shared__ float sprev;
    const int b = blockIdx.x, tid = threadIdx.x;
    float prev;
    if (s == 0) {
        prev = g_prev0[b];
    } else {
        float v = g_relu[b * FCH + tid] * f2W[tid];
        #pragma unroll
        for (int o = 16; o > 0; o >>= 1) v += __shfl_down_sync(0xffffffffu, v, o);
        if ((tid & 31) == 0) sred[tid >> 5] = v;
        __syncthreads();
        if (tid < 8) {
            float xv = sred[tid];
            #pragma unroll
            for (int o = 4; o > 0; o >>= 1) xv += __shfl_down_sync(0xffu, xv, o);
            if (tid == 0) sprev = xv + f2b[0];
        }
        __syncthreads();
        prev = sprev;
        if (tid == 0) dout[b * OL + (s - 1)] = prev;
    }
    if (tid == 0) g_prev[b] = prev;
    if (!do_attn) return;

    if (tid < 128)
        ssc[tid] = (prev * g_Asc[b * T_ + tid] + g_Csc[b * T_ + tid]) * 0.0625f;
    __syncthreads();
    if (tid < 32) {
        float m = -1e30f;
        for (int i = tid; i < 128; i += 32) m = fmaxf(m, ssc[i]);
        #pragma unroll
        for (int o = 16; o > 0; o >>= 1) m = fmaxf(m, __shfl_down_sync(0xffffffffu, m, o));
        if (tid == 0) sred[0] = m;
    }
    __syncthreads();
    float mx = sred[0];
    if (tid < 128) ssc[tid] = expf(ssc[tid] - mx);
    __syncthreads();
    if (tid < 32) {
        float sum = 0.f;
        for (int i = tid; i < 128; i += 32) sum += ssc[i];
        #pragma unroll
        for (int o = 16; o > 0; o >>= 1) sum += __shfl_down_sync(0xffffffffu, sum, o);
        if (tid == 0) sred[1] = sum;
    }
    __syncthreads();
    float inv = 1.f / sred[1];
    const __half* hp = g_hs + (size_t)b * T_ * H_ + tid;
    float accv = 0.f;
    #pragma unroll 4
    for (int t2 = 0; t2 < T_; t2++)
        accv += ssc[t2] * __half2float(hp[(size_t)t2 * H_]);
    g_ctx[b * H_ + tid] = accv * inv;
}

// ---- decoder elementwise GRU: x=prev (scalar), h=ctx ----
__global__ void dec_gru(const float* __restrict__ dWih, const float* __restrict__ dbih,
                        const float* __restrict__ dbhh)
{
    int i = blockIdx.x * blockDim.x + threadIdx.x;
    if (i >= B_ * H_) return;
    int b = i >> 8, k = i & 255;
    float pv = g_prev[b];
    const float* gh = g_gh + b * G3;
    float r = sigf(pv * dWih[k] + dbih[k] + gh[k] + dbhh[k]);
    float z = sigf(pv * dWih[H_ + k] + dbih[H_ + k] + gh[H_ + k] + dbhh[H_ + k]);
    float n = tanhf(pv * dWih[2 * H_ + k] + dbih[2 * H_ + k] + r * (gh[2 * H_ + k] + dbhh[2 * H_ + k]));
    g_hd[i] = (1.f - z) * n + z * g_ctx[i];
}

// ---- host launch ----
extern "C" void kernel_launch(void* const* d_in, const int* in_sizes, int n_in,
                              void* d_out, int out_size)
{
    const float* x    = (const float*)d_in[0];
    const float* h0   = (const float*)d_in[1];
    const float* eWih = (const float*)d_in[2];
    const float* eWhh = (const float*)d_in[3];
    const float* ebih = (const float*)d_in[4];
    const float* ebhh = (const float*)d_in[5];
    const float* dWih = (const float*)d_in[6];
    const float* dWhh = (const float*)d_in[7];
    const float* dbih = (const float*)d_in[8];
    const float* dbhh = (const float*)d_in[9];
    const float* Wq   = (const float*)d_in[10];
    const float* bq   = (const float*)d_in[11];
    const float* f1W  = (const float*)d_in[12];
    const float* f1b  = (const float*)d_in[13];
    const float* f2W  = (const float*)d_in[14];
    const float* f2b  = (const float*)d_in[15];
    float* out = (float*)d_out;

    void *p_gi, *p_gh, *p_h, *p_ctx, *p_hd, *p_relu;
    void *p_ihh, *p_ihl, *p_ehh, *p_ehl, *p_dhh, *p_dhl, *p_f1h, *p_f1l;
    cudaGetSymbolAddress(&p_gi, g_gi);
    cudaGetSymbolAddress(&p_gh, g_gh);
    cudaGetSymbolAddress(&p_h, g_h);
    cudaGetSymbolAddress(&p_ctx, g_ctx);
    cudaGetSymbolAddress(&p_hd, g_hd);
    cudaGetSymbolAddress(&p_relu, g_relu);
    cudaGetSymbolAddress(&p_ihh, ih_hi); cudaGetSymbolAddress(&p_ihl, ih_lo);
    cudaGetSymbolAddress(&p_ehh, eh_hi); cudaGetSymbolAddress(&p_ehl, eh_lo);
    cudaGetSymbolAddress(&p_dhh, dh_hi); cudaGetSymbolAddress(&p_dhl, dh_lo);
    cudaGetSymbolAddress(&p_f1h, f1_hi); cudaGetSymbolAddress(&p_f1l, f1_lo);

    prep_weights<<<(G3 * F_ + 2 * G3 * H_ + FCH * H_ + 255) / 256, 256>>>(eWih, eWhh, dWhh, f1W);
    prep_state<<<(B_ * H_ + 255) / 256, 256>>>(x, h0);

    // gi = X @ Wih^T for all timesteps (X viewed as [B*T, F])
    gemm_split<<<dim3(B_ * T_ / 128, G3 / 64), 256>>>(
        x, F_, (__nv_bfloat16*)p_ihh, (__nv_bfloat16*)p_ihl,
        (float*)p_gi, G3, F_, nullptr, 0);

    // encoder recurrence
    int pin = 0;
    for (int t = 0; t < T_; t++) {
        gemm_split<<<dim3(B_ / 128, G3 / 64), 256>>>(
            (float*)p_h + (size_t)pin * B_ * H_, H_,
            (__nv_bfloat16*)p_ehh, (__nv_bfloat16*)p_ehl,
            (float*)p_gh, G3, H_, nullptr, 0);
        enc_elem<<<(B_ * H_ + 255) / 256, 256>>>(ebih, ebhh, t, pin);
        pin ^= 1;
    }

    attn_pre<<<B_ * T_ / 8, 256>>>(Wq, bq);

    // decoder: s=0..OL-1 full steps; s=OL computes final fc2 output only
    for (int s = 0; s <= OL; s++) {
        dec_attn<<<B_, 256>>>(f2W, f2b, out, s, s < OL ? 1 : 0);
        if (s == OL) break;
        gemm_split<<<dim3(B_ / 128, G3 / 64), 256>>>(
            (float*)p_ctx, H_, (__nv_bfloat16*)p_dhh, (__nv_bfloat16*)p_dhl,
            (float*)p_gh, G3, H_, nullptr, 0);
        dec_gru<<<(B_ * H_ + 255) / 256, 256>>>(dWih, dbih, dbhh);
        gemm_split<<<dim3(B_ / 128, FCH / 64), 256>>>(
            (float*)p_hd, H_, (__nv_bfloat16*)p_f1h, (__nv_bfloat16*)p_f1l,
            (float*)p_relu, FCH, H_, f1b, 1);
    }
}